// round 11
// baseline (speedup 1.0000x reference)
#include <cuda_runtime.h>
#include <cstdint>
#include <cstddef>

#define NB    64      // batch
#define NS    512     // seq len
#define NE    512     // embed dim
#define NH    1024    // hidden
#define NG    4096    // 4*H
#define NCTA  128     // persistent CTAs (1 per SM)

typedef unsigned long long u64;

// ---------------- scratch (device globals: sanctioned, no allocation) ----------------
__device__ float g_xproj[(size_t)NS * NB * NG];   // 512 MB: [s][b][4H]
__device__ float g_hbuf[2][NB * NH];              // double-buffered h
__device__ unsigned int g_bar_arrive;
__device__ unsigned int g_bar_gen;

__global__ void init_kernel() {
    g_bar_arrive = 0u;
    g_bar_gen = 0u;
}

__device__ __forceinline__ float sigm(float v) { return 1.0f / (1.0f + __expf(-v)); }

// ---- packed fp32x2 helpers (Blackwell dual-rate fp32; ptxas never auto-fuses) ----
__device__ __forceinline__ u64 pk2(float lo, float hi) {
    u64 r; asm("mov.b64 %0, {%1, %2};" : "=l"(r) : "f"(lo), "f"(hi)); return r;
}
__device__ __forceinline__ void upk2(u64 v, float& lo, float& hi) {
    asm("mov.b64 {%0, %1}, %2;" : "=f"(lo), "=f"(hi) : "l"(v));
}
__device__ __forceinline__ u64 ff2(u64 a, u64 b, u64 c) {   // a*b + c, both lanes
    u64 d; asm("fma.rn.f32x2 %0, %1, %2, %3;" : "=l"(d) : "l"(a), "l"(b), "l"(c)); return d;
}

// =====================================================================
// Kernel A: xproj[s][b][g] = sum_e emb[x[b][s]][e] * W_ih[g][e] + b_ih[g]
// GEMM M=32768, N=4096, K=512. BM=BN=128, BK=16, 256 thr, 8x8/thread.
// fp32x2 paired along N; skewed smem phys(c)=c+4*(c>>5). 2 CTAs/SM.
// =====================================================================
#define AST 140   // skewed row stride (floats); max phys = 139

__global__ __launch_bounds__(256, 2)
void xproj_kernel(const int* __restrict__ x,
                  const float* __restrict__ emb,
                  const float* __restrict__ W_ih,
                  const float* __restrict__ b_ih)
{
    __shared__ __align__(16) float As[16 * AST];
    __shared__ __align__(16) float Bs[16 * AST];

    const int tid = threadIdx.x;
    const int nt = blockIdx.x;       // 0..31
    const int mt = blockIdx.y;       // 0..255
    const int m0 = mt * 128;
    const int n0 = nt * 128;

    const int lrow = tid >> 2;       // 0..63
    const int lch  = tid & 3;        // float4 chunk within 16-k slab

    const int mA0 = m0 + lrow;
    const int mA1 = mA0 + 64;
    const int tok0 = x[(mA0 & 63) * NS + (mA0 >> 6)];
    const int tok1 = x[(mA1 & 63) * NS + (mA1 >> 6)];
    const float4* a0p = (const float4*)(emb + (size_t)tok0 * NE);
    const float4* a1p = (const float4*)(emb + (size_t)tok1 * NE);
    const float4* b0p = (const float4*)(W_ih + (size_t)(n0 + lrow) * NE);
    const float4* b1p = (const float4*)(W_ih + (size_t)(n0 + lrow + 64) * NE);

    const int tx = tid & 15;         // n-dir thread coord
    const int ty = tid >> 4;         // m-dir thread coord

    const int pm0 = lrow + ((lrow >> 5) << 2);
    const int pm1 = (lrow + 64) + (((lrow + 64) >> 5) << 2);
    const int pa  = ty * 8 + ((ty >> 2) << 2);
    const int pb  = tx * 8 + ((tx >> 2) << 2);

    u64 acc[8][4];
#pragma unroll
    for (int i = 0; i < 8; i++)
#pragma unroll
        for (int jp = 0; jp < 4; jp++) acc[i][jp] = 0ull;

    float4 av0 = a0p[lch], av1 = a1p[lch], bv0 = b0p[lch], bv1 = b1p[lch];

    for (int kt = 0; kt < 32; kt++) {
        const int kl = lch * 4;
        As[(kl + 0) * AST + pm0] = av0.x; As[(kl + 1) * AST + pm0] = av0.y;
        As[(kl + 2) * AST + pm0] = av0.z; As[(kl + 3) * AST + pm0] = av0.w;
        As[(kl + 0) * AST + pm1] = av1.x; As[(kl + 1) * AST + pm1] = av1.y;
        As[(kl + 2) * AST + pm1] = av1.z; As[(kl + 3) * AST + pm1] = av1.w;
        Bs[(kl + 0) * AST + pm0] = bv0.x; Bs[(kl + 1) * AST + pm0] = bv0.y;
        Bs[(kl + 2) * AST + pm0] = bv0.z; Bs[(kl + 3) * AST + pm0] = bv0.w;
        Bs[(kl + 0) * AST + pm1] = bv1.x; Bs[(kl + 1) * AST + pm1] = bv1.y;
        Bs[(kl + 2) * AST + pm1] = bv1.z; Bs[(kl + 3) * AST + pm1] = bv1.w;
        __syncthreads();

        if (kt < 31) {               // prefetch next slab under compute
            const int kc = (kt + 1) * 4 + lch;
            av0 = a0p[kc]; av1 = a1p[kc]; bv0 = b0p[kc]; bv1 = b1p[kc];
        }

#pragma unroll
        for (int k = 0; k < 16; k++) {
            const float4 aa0 = *(const float4*)&As[k * AST + pa];
            const float4 aa1 = *(const float4*)&As[k * AST + pa + 4];
            const ulonglong2 bq0 = *(const ulonglong2*)&Bs[k * AST + pb];
            const ulonglong2 bq1 = *(const ulonglong2*)&Bs[k * AST + pb + 4];
            const u64 b2[4] = {bq0.x, bq0.y, bq1.x, bq1.y};
            const float a[8] = {aa0.x, aa0.y, aa0.z, aa0.w, aa1.x, aa1.y, aa1.z, aa1.w};
#pragma unroll
            for (int i = 0; i < 8; i++) {
                const u64 ad = pk2(a[i], a[i]);   // alu mov, hidden in free slots
#pragma unroll
                for (int jp = 0; jp < 4; jp++)
                    acc[i][jp] = ff2(ad, b2[jp], acc[i][jp]);
            }
        }
        __syncthreads();
    }

    float bias[8];
#pragma unroll
    for (int j = 0; j < 8; j++) bias[j] = b_ih[n0 + tx * 8 + j];
#pragma unroll
    for (int i = 0; i < 8; i++) {
        float o[8];
#pragma unroll
        for (int jp = 0; jp < 4; jp++) upk2(acc[i][jp], o[2 * jp], o[2 * jp + 1]);
        const size_t base = (size_t)(m0 + ty * 8 + i) * NG + (n0 + tx * 8);
        float4 o0, o1;
        o0.x = o[0] + bias[0]; o0.y = o[1] + bias[1];
        o0.z = o[2] + bias[2]; o0.w = o[3] + bias[3];
        o1.x = o[4] + bias[4]; o1.y = o[5] + bias[5];
        o1.z = o[6] + bias[6]; o1.w = o[7] + bias[7];
        __stcs((float4*)&g_xproj[base], o0);       // evict-first: 512MB stream
        __stcs((float4*)&g_xproj[base + 4], o1);
    }
}

// =====================================================================
// Kernel B: persistent LSTM recurrence, fp32x2 along K, 512 threads/CTA
// (4 warps/SMSP for latency hiding). CTA owns 8 hidden units = 32 gate
// rows of W_hh resident in smem. 4 k-slices x 128 positions; 4 rows x 4
// batches register tile. Double-buffered h tiles, swizzle cs=gc^(gb>>3).
// =====================================================================
__device__ __forceinline__ void grid_barrier(unsigned int nb, unsigned int& gen)
{
    __syncthreads();
    if (threadIdx.x == 0) {
        __threadfence();
        const unsigned int target = gen + 1u;
        const unsigned int cnt = atomicAdd(&g_bar_arrive, 1u) + 1u;
        if (cnt == target * nb) {
            atomicExch(&g_bar_gen, target);
        } else {
            while (*((volatile unsigned int*)&g_bar_gen) < target) { __nanosleep(32); }
        }
        __threadfence();
    }
    gen++;
    __syncthreads();
}

__global__ __launch_bounds__(512, 1)
void lstm_kernel(const float* __restrict__ h0, const float* __restrict__ c0,
                 const float* __restrict__ W_hh, const float* __restrict__ b_hh,
                 const float* __restrict__ fc_w, const float* __restrict__ fc_b,
                 float* __restrict__ out, int out_size)
{
    extern __shared__ __align__(16) float smem[];
    float* sw   = smem;                    // [32][1028] W_hh slice      (131584 B)
    float* shb  = smem + 32 * 1028;        // 2 x [64][128] h tiles      ( 65536 B)
    float* sred = shb + 2 * 8192;          // [4][128*17] k-slice partials (34816 B)
                                           // total 231936 B <= 232448

    const int tid = threadIdx.x;
    const int cta = blockIdx.x;
    const int j0 = cta * 8;

    // ---- W_hh slice: local row r holds gate row (r>>3)*NH + j0 + (r&7)
    for (int i = tid; i < 32 * 256; i += 512) {
        const int r = i >> 8;
        const int c4 = i & 255;
        const int q = r >> 3, u = r & 7;
        ((float4*)(sw + r * 1028))[c4] =
            ((const float4*)(W_hh + (size_t)(q * NH + j0 + u) * NH))[c4];
    }

    // ---- gate-update mapping: one (batch, unit) cell per thread
    const int b  = tid & 63;
    const int jl = tid >> 6;               // 0..7

    float creg = c0[b * NH + j0 + jl];
    g_hbuf[0][b * NH + j0 + jl] = h0[b * NH + j0 + jl];

    float bh[4];
#pragma unroll
    for (int q = 0; q < 4; q++) bh[q] = b_hh[q * NH + j0 + jl];

    // ---- GEMM mapping: 4 k-slices x 128 positions; 4 gate-rows x 4 batches
    const int ks  = tid >> 7;              // k-slice 0..3
    const int pos = tid & 127;
    const int rb  = pos >> 4;              // unit 0..7 (rows rb, rb+8, rb+16, rb+24)
    const int bb  = pos & 15;              // batch quad (hb = bb*4 + j)
    const int csx = bb >> 1;               // = (hb>>3) for all j<4

    unsigned int gen = 0;
    grid_barrier(NCTA, gen);               // h0 visible everywhere

    float hlast = 0.0f;

    for (int s = 0; s < NS; s++) {
        const float* hread  = g_hbuf[s & 1];
        float*       hwrite = g_hbuf[(s + 1) & 1];

        // xproj gate inputs for this step (latency hidden under GEMM)
        const size_t xbase = ((size_t)s * NB + b) * NG + j0 + jl;
        float xg[4];
#pragma unroll
        for (int q = 0; q < 4; q++) xg[q] = __ldcg(&g_xproj[xbase + q * NH]);

        u64 acc[4][4];                     // [gate-row][batch] even/odd-k pairs
#pragma unroll
        for (int i = 0; i < 4; i++)
#pragma unroll
            for (int j = 0; j < 4; j++) acc[i][j] = 0ull;

        // prologue: fetch + store tile 0 (2048 float4 / 512 thr = 4 each)
        float4 pf[4];
#pragma unroll
        for (int i = 0; i < 4; i++) {
            const int g = tid + (i << 9); const int gb = g >> 5, gc = g & 31;
            pf[i] = __ldcg((const float4*)(hread + gb * NH + (gc << 2)));
        }
#pragma unroll
        for (int i = 0; i < 4; i++) {
            const int g = tid + (i << 9); const int gb = g >> 5, gc = g & 31;
            const int cs = gc ^ (gb >> 3);
            *(float4*)(shb + gb * 128 + (cs << 2)) = pf[i];
        }

#pragma unroll 2
        for (int kt = 0; kt < 8; kt++) {
            __syncthreads();
            const float* scur = shb + ((kt & 1) << 13);
            float*       snxt = shb + (((kt + 1) & 1) << 13);

            if (kt < 7) {                  // prefetch next tile under compute
#pragma unroll
                for (int i = 0; i < 4; i++) {
                    const int g = tid + (i << 9); const int gb = g >> 5, gc = g & 31;
                    pf[i] = __ldcg((const float4*)(hread + gb * NH + ((kt + 1) << 7) + (gc << 2)));
                }
            }

#pragma unroll
            for (int t = 0; t < 8; t++) {
                const int k4   = ks + (t << 2);
                const int wcol = (kt << 7) + (k4 << 2);
                const ulonglong2 w0 = *(const ulonglong2*)(sw + (rb +  0) * 1028 + wcol);
                const ulonglong2 w1 = *(const ulonglong2*)(sw + (rb +  8) * 1028 + wcol);
                const ulonglong2 w2 = *(const ulonglong2*)(sw + (rb + 16) * 1028 + wcol);
                const ulonglong2 w3 = *(const ulonglong2*)(sw + (rb + 24) * 1028 + wcol);
                const int cs = k4 ^ csx;
#pragma unroll
                for (int j = 0; j < 4; j++) {
                    const int hb = (bb << 2) + j;
                    const ulonglong2 hv = *(const ulonglong2*)(scur + hb * 128 + (cs << 2));
                    acc[0][j] = ff2(w0.x, hv.x, acc[0][j]);
                    acc[0][j] = ff2(w0.y, hv.y, acc[0][j]);
                    acc[1][j] = ff2(w1.x, hv.x, acc[1][j]);
                    acc[1][j] = ff2(w1.y, hv.y, acc[1][j]);
                    acc[2][j] = ff2(w2.x, hv.x, acc[2][j]);
                    acc[2][j] = ff2(w2.y, hv.y, acc[2][j]);
                    acc[3][j] = ff2(w3.x, hv.x, acc[3][j]);
                    acc[3][j] = ff2(w3.y, hv.y, acc[3][j]);
                }
            }

            if (kt < 7) {                  // commit prefetched tile
#pragma unroll
                for (int i = 0; i < 4; i++) {
                    const int g = tid + (i << 9); const int gb = g >> 5, gc = g & 31;
                    const int cs = gc ^ (gb >> 3);
                    *(float4*)(snxt + gb * 128 + (cs << 2)) = pf[i];
                }
            }
        }

        // ---- fold pairs, cross-slice reduction (stride 17: conflict-free)
#pragma unroll
        for (int i = 0; i < 4; i++)
#pragma unroll
            for (int j = 0; j < 4; j++) {
                float lo, hi; upk2(acc[i][j], lo, hi);
                sred[ks * 2176 + pos * 17 + (i << 2) + j] = lo + hi;
            }
        __syncthreads();

        // ---- gate math + state update (1 cell/thread)
        // cell (row q*8+jl, batch b) -> pos' = jl*16 + (b>>2), slot q*4 + (b&3)
        {
            const int base = (jl * 16 + (b >> 2)) * 17 + (b & 3);
            float gs[4];
#pragma unroll
            for (int q = 0; q < 4; q++) {
                const int idx = base + (q << 2);
                gs[q] = sred[idx] + sred[2176 + idx] + sred[4352 + idx] + sred[6528 + idx]
                        + xg[q] + bh[q];
            }
            const float ig = sigm(gs[0]), fg = sigm(gs[1]);
            const float gg = tanhf(gs[2]), og = sigm(gs[3]);
            creg = fg * creg + ig * gg;
            hlast = og * tanhf(creg);
            hwrite[b * NH + j0 + jl] = hlast;
        }

        grid_barrier(NCTA, gen);
    }

    // ---- outputs: [sig_out(64) | h(64x1024) | c(64x1024)]
    if (out_size >= 64 + NB * NH)
        out[64 + b * NH + j0 + jl] = hlast;
    if (out_size >= 64 + 2 * NB * NH)
        out[64 + NB * NH + b * NH + j0 + jl] = creg;
    if (cta == 0 && tid < 64 && out_size >= 64) {
        const float* hfin = g_hbuf[0];     // NS even -> final h in buffer 0
        float a = fc_b[0];
        for (int k = 0; k < NH; k += 4) {
            const float4 hv = __ldcg((const float4*)(hfin + tid * NH + k));
            const float4 wv = *(const float4*)(fc_w + k);
            a += hv.x * wv.x; a += hv.y * wv.y; a += hv.z * wv.z; a += hv.w * wv.w;
        }
        out[tid] = sigm(a);
    }
}

// =====================================================================
extern "C" void kernel_launch(void* const* d_in, const int* in_sizes, int n_in,
                              void* d_out, int out_size)
{
    const int*   x    = (const int*)d_in[0];
    const float* h0   = (const float*)d_in[1];
    const float* c0   = (const float*)d_in[2];
    const float* emb  = (const float*)d_in[3];
    const float* W_ih = (const float*)d_in[4];
    const float* W_hh = (const float*)d_in[5];
    const float* b_ih = (const float*)d_in[6];
    const float* b_hh = (const float*)d_in[7];
    const float* fc_w = (const float*)d_in[8];
    const float* fc_b = (const float*)d_in[9];
    float* out = (float*)d_out;

    const int lstm_smem = (32 * 1028 + 2 * 8192 + 4 * 2176) * (int)sizeof(float); // 231936 B
    cudaFuncSetAttribute(lstm_kernel, cudaFuncAttributeMaxDynamicSharedMemorySize, lstm_smem);

    init_kernel<<<1, 1>>>();                              // reset grid-barrier state
    dim3 grid_x(32, 256);                                 // N-tiles x M-tiles
    xproj_kernel<<<grid_x, 256>>>(x, emb, W_ih, b_ih);
    lstm_kernel<<<NCTA, 512, lstm_smem>>>(h0, c0, W_hh, b_hh, fc_w, fc_b, out, out_size);
}

// round 12
// speedup vs baseline: 1.2957x; 1.2957x over previous
#include <cuda_runtime.h>
#include <cstdint>
#include <cstddef>

#define NB    64      // batch
#define NS    512     // seq len
#define NE    512     // embed dim
#define NH    1024    // hidden
#define NG    4096    // 4*H
#define NCTA  128     // persistent CTAs (1 per SM)

typedef unsigned long long u64;

// ---------------- scratch (device globals: sanctioned, no allocation) ----------------
__device__ float g_xproj[(size_t)NS * NB * NG];   // 512 MB: [s][b][4H]
__device__ float g_hbuf[2][NB * NH];              // double-buffered h
__device__ u64 g_bar_ticket;                      // monotonic arrival tickets
__device__ u64 g_bar_gen;                         // monotonic release count

__device__ __forceinline__ float sigm(float v) { return 1.0f / (1.0f + __expf(-v)); }

// ---- packed fp32x2 helpers (Blackwell dual-rate fp32; ptxas never auto-fuses) ----
__device__ __forceinline__ u64 pk2(float lo, float hi) {
    u64 r; asm("mov.b64 %0, {%1, %2};" : "=l"(r) : "f"(lo), "f"(hi)); return r;
}
__device__ __forceinline__ void upk2(u64 v, float& lo, float& hi) {
    asm("mov.b64 {%0, %1}, %2;" : "=f"(lo), "=f"(hi) : "l"(v));
}
__device__ __forceinline__ u64 ff2(u64 a, u64 b, u64 c) {   // a*b + c, both lanes
    u64 d; asm("fma.rn.f32x2 %0, %1, %2, %3;" : "=l"(d) : "l"(a), "l"(b), "l"(c)); return d;
}

// =====================================================================
// Kernel A: xproj[s][b][g] = sum_e emb[x[b][s]][e] * W_ih[g][e] + b_ih[g]
// GEMM M=32768, N=4096, K=512. BM=BN=128, BK=16, 256 thr, 8x8/thread.
// fp32x2 paired along N; skewed smem phys(c)=c+4*(c>>5). 2 CTAs/SM.
// =====================================================================
#define AST 140   // skewed row stride (floats); max phys = 139

__global__ __launch_bounds__(256, 2)
void xproj_kernel(const int* __restrict__ x,
                  const float* __restrict__ emb,
                  const float* __restrict__ W_ih,
                  const float* __restrict__ b_ih)
{
    __shared__ __align__(16) float As[16 * AST];
    __shared__ __align__(16) float Bs[16 * AST];

    const int tid = threadIdx.x;
    const int nt = blockIdx.x;       // 0..31
    const int mt = blockIdx.y;       // 0..255
    const int m0 = mt * 128;
    const int n0 = nt * 128;

    const int lrow = tid >> 2;       // 0..63
    const int lch  = tid & 3;        // float4 chunk within 16-k slab

    const int mA0 = m0 + lrow;
    const int mA1 = mA0 + 64;
    const int tok0 = x[(mA0 & 63) * NS + (mA0 >> 6)];
    const int tok1 = x[(mA1 & 63) * NS + (mA1 >> 6)];
    const float4* a0p = (const float4*)(emb + (size_t)tok0 * NE);
    const float4* a1p = (const float4*)(emb + (size_t)tok1 * NE);
    const float4* b0p = (const float4*)(W_ih + (size_t)(n0 + lrow) * NE);
    const float4* b1p = (const float4*)(W_ih + (size_t)(n0 + lrow + 64) * NE);

    const int tx = tid & 15;         // n-dir thread coord
    const int ty = tid >> 4;         // m-dir thread coord

    const int pm0 = lrow + ((lrow >> 5) << 2);
    const int pm1 = (lrow + 64) + (((lrow + 64) >> 5) << 2);
    const int pa  = ty * 8 + ((ty >> 2) << 2);
    const int pb  = tx * 8 + ((tx >> 2) << 2);

    u64 acc[8][4];
#pragma unroll
    for (int i = 0; i < 8; i++)
#pragma unroll
        for (int jp = 0; jp < 4; jp++) acc[i][jp] = 0ull;

    float4 av0 = a0p[lch], av1 = a1p[lch], bv0 = b0p[lch], bv1 = b1p[lch];

    for (int kt = 0; kt < 32; kt++) {
        const int kl = lch * 4;
        As[(kl + 0) * AST + pm0] = av0.x; As[(kl + 1) * AST + pm0] = av0.y;
        As[(kl + 2) * AST + pm0] = av0.z; As[(kl + 3) * AST + pm0] = av0.w;
        As[(kl + 0) * AST + pm1] = av1.x; As[(kl + 1) * AST + pm1] = av1.y;
        As[(kl + 2) * AST + pm1] = av1.z; As[(kl + 3) * AST + pm1] = av1.w;
        Bs[(kl + 0) * AST + pm0] = bv0.x; Bs[(kl + 1) * AST + pm0] = bv0.y;
        Bs[(kl + 2) * AST + pm0] = bv0.z; Bs[(kl + 3) * AST + pm0] = bv0.w;
        Bs[(kl + 0) * AST + pm1] = bv1.x; Bs[(kl + 1) * AST + pm1] = bv1.y;
        Bs[(kl + 2) * AST + pm1] = bv1.z; Bs[(kl + 3) * AST + pm1] = bv1.w;
        __syncthreads();

        if (kt < 31) {               // prefetch next slab under compute
            const int kc = (kt + 1) * 4 + lch;
            av0 = a0p[kc]; av1 = a1p[kc]; bv0 = b0p[kc]; bv1 = b1p[kc];
        }

#pragma unroll
        for (int k = 0; k < 16; k++) {
            const float4 aa0 = *(const float4*)&As[k * AST + pa];
            const float4 aa1 = *(const float4*)&As[k * AST + pa + 4];
            const ulonglong2 bq0 = *(const ulonglong2*)&Bs[k * AST + pb];
            const ulonglong2 bq1 = *(const ulonglong2*)&Bs[k * AST + pb + 4];
            const u64 b2[4] = {bq0.x, bq0.y, bq1.x, bq1.y};
            const float a[8] = {aa0.x, aa0.y, aa0.z, aa0.w, aa1.x, aa1.y, aa1.z, aa1.w};
#pragma unroll
            for (int i = 0; i < 8; i++) {
                const u64 ad = pk2(a[i], a[i]);   // alu mov, hidden in free slots
#pragma unroll
                for (int jp = 0; jp < 4; jp++)
                    acc[i][jp] = ff2(ad, b2[jp], acc[i][jp]);
            }
        }
        __syncthreads();
    }

    float bias[8];
#pragma unroll
    for (int j = 0; j < 8; j++) bias[j] = b_ih[n0 + tx * 8 + j];
#pragma unroll
    for (int i = 0; i < 8; i++) {
        float o[8];
#pragma unroll
        for (int jp = 0; jp < 4; jp++) upk2(acc[i][jp], o[2 * jp], o[2 * jp + 1]);
        const size_t base = (size_t)(m0 + ty * 8 + i) * NG + (n0 + tx * 8);
        float4 o0, o1;
        o0.x = o[0] + bias[0]; o0.y = o[1] + bias[1];
        o0.z = o[2] + bias[2]; o0.w = o[3] + bias[3];
        o1.x = o[4] + bias[4]; o1.y = o[5] + bias[5];
        o1.z = o[6] + bias[6]; o1.w = o[7] + bias[7];
        __stcs((float4*)&g_xproj[base], o0);       // evict-first: 512MB stream
        __stcs((float4*)&g_xproj[base + 4], o1);
    }
}

// =====================================================================
// Replay-safe grid barrier: monotonic u64 ticket/generation counters.
// Instance i gathers tickets [i*NCTA, (i+1)*NCTA); last arriver bumps gen.
// Instances are strictly sequential, so no reset kernel is needed and
// state carries harmlessly across CUDA-graph replays.
// =====================================================================
__device__ __forceinline__ void grid_barrier()
{
    __syncthreads();
    if (threadIdx.x == 0) {
        __threadfence();
        const u64 t = atomicAdd(&g_bar_ticket, 1ull);
        const u64 inst = t / NCTA;
        if ((t % NCTA) == NCTA - 1) {
            atomicAdd(&g_bar_gen, 1ull);           // release: gen -> inst+1
        } else {
            while (*((volatile u64*)&g_bar_gen) <= inst) { }
        }
        __threadfence();
    }
    __syncthreads();
}

// =====================================================================
// Kernel B: persistent LSTM recurrence, fp32x2 along K, 512 threads/CTA
// (4 warps/SMSP). Warp footprint engineered for banking:
//   bb = (pos&7)|((pos>>6)<<3), rb = (pos>>3)&7  -> per warp: 8 bb x 4 rb
//   store swizzle cs = gc ^ ((gb>>2)&7)  -> stores conflict-free (4 wf)
//   read  swizzle cs = k4 ^ (bb&7)       -> 1 wavefront, 4-way broadcast
// =====================================================================
__global__ __launch_bounds__(512, 1)
void lstm_kernel(const float* __restrict__ h0, const float* __restrict__ c0,
                 const float* __restrict__ W_hh, const float* __restrict__ b_hh,
                 const float* __restrict__ fc_w, const float* __restrict__ fc_b,
                 float* __restrict__ out, int out_size)
{
    extern __shared__ __align__(16) float smem[];
    float* sw   = smem;                    // [32][1028] W_hh slice      (131584 B)
    float* shb  = smem + 32 * 1028;        // 2 x [64][128] h tiles      ( 65536 B)
    float* sred = shb + 2 * 8192;          // [4][128*17] k-slice partials (34816 B)
                                           // total 231936 B <= 232448

    const int tid = threadIdx.x;
    const int cta = blockIdx.x;
    const int j0 = cta * 8;

    // ---- W_hh slice: local row r holds gate row (r>>3)*NH + j0 + (r&7)
    for (int i = tid; i < 32 * 256; i += 512) {
        const int r = i >> 8;
        const int c4 = i & 255;
        const int q = r >> 3, u = r & 7;
        ((float4*)(sw + r * 1028))[c4] =
            ((const float4*)(W_hh + (size_t)(q * NH + j0 + u) * NH))[c4];
    }

    // ---- gate-update mapping: one (batch, unit) cell per thread
    const int b  = tid & 63;
    const int jl = tid >> 6;               // 0..7

    float creg = c0[b * NH + j0 + jl];
    g_hbuf[0][b * NH + j0 + jl] = h0[b * NH + j0 + jl];

    float bh[4];
#pragma unroll
    for (int q = 0; q < 4; q++) bh[q] = b_hh[q * NH + j0 + jl];

    // ---- GEMM mapping: 4 k-slices x 128 positions; 4 gate-rows x 4 batches.
    // Warp-local: bb spans 8 values (b0..b2), rb spans 4 (b3,b4).
    const int ks  = tid >> 7;                       // k-slice 0..3
    const int pos = tid & 127;
    const int bb  = (pos & 7) | ((pos >> 6) << 3);  // batch quad 0..15
    const int rb  = (pos >> 3) & 7;                 // unit 0..7
    const int csx = bb & 7;                         // = (hb>>2)&7 for j<4

    grid_barrier();                        // h0 visible everywhere

    float hlast = 0.0f;

    for (int s = 0; s < NS; s++) {
        const float* hread  = g_hbuf[s & 1];
        float*       hwrite = g_hbuf[(s + 1) & 1];

        // xproj gate inputs for this step (latency hidden under GEMM)
        const size_t xbase = ((size_t)s * NB + b) * NG + j0 + jl;
        float xg[4];
#pragma unroll
        for (int q = 0; q < 4; q++) xg[q] = __ldcg(&g_xproj[xbase + q * NH]);

        u64 acc[4][4];                     // [gate][batch] even/odd-k pairs
#pragma unroll
        for (int i = 0; i < 4; i++)
#pragma unroll
            for (int j = 0; j < 4; j++) acc[i][j] = 0ull;

        // prologue: fetch + store tile 0 (2048 float4 / 512 thr = 4 each)
        float4 pf[4];
#pragma unroll
        for (int i = 0; i < 4; i++) {
            const int g = tid + (i << 9); const int gb = g >> 5, gc = g & 31;
            pf[i] = __ldcg((const float4*)(hread + gb * NH + (gc << 2)));
        }
#pragma unroll
        for (int i = 0; i < 4; i++) {
            const int g = tid + (i << 9); const int gb = g >> 5, gc = g & 31;
            const int cs = gc ^ ((gb >> 2) & 7);
            *(float4*)(shb + gb * 128 + (cs << 2)) = pf[i];
        }

#pragma unroll 2
        for (int kt = 0; kt < 8; kt++) {
            __syncthreads();
            const float* scur = shb + ((kt & 1) << 13);
            float*       snxt = shb + (((kt + 1) & 1) << 13);

            if (kt < 7) {                  // prefetch next tile under compute
#pragma unroll
                for (int i = 0; i < 4; i++) {
                    const int g = tid + (i << 9); const int gb = g >> 5, gc = g & 31;
                    pf[i] = __ldcg((const float4*)(hread + gb * NH + ((kt + 1) << 7) + (gc << 2)));
                }
            }

#pragma unroll
            for (int t = 0; t < 8; t++) {
                const int k4   = ks + (t << 2);
                const int wcol = (kt << 7) + (k4 << 2);
                const ulonglong2 w0 = *(const ulonglong2*)(sw + (rb +  0) * 1028 + wcol);
                const ulonglong2 w1 = *(const ulonglong2*)(sw + (rb +  8) * 1028 + wcol);
                const ulonglong2 w2 = *(const ulonglong2*)(sw + (rb + 16) * 1028 + wcol);
                const ulonglong2 w3 = *(const ulonglong2*)(sw + (rb + 24) * 1028 + wcol);
                const int cs = k4 ^ csx;
#pragma unroll
                for (int j = 0; j < 4; j++) {
                    const int hb = (bb << 2) + j;
                    const ulonglong2 hv = *(const ulonglong2*)(scur + hb * 128 + (cs << 2));
                    acc[0][j] = ff2(w0.x, hv.x, acc[0][j]);
                    acc[0][j] = ff2(w0.y, hv.y, acc[0][j]);
                    acc[1][j] = ff2(w1.x, hv.x, acc[1][j]);
                    acc[1][j] = ff2(w1.y, hv.y, acc[1][j]);
                    acc[2][j] = ff2(w2.x, hv.x, acc[2][j]);
                    acc[2][j] = ff2(w2.y, hv.y, acc[2][j]);
                    acc[3][j] = ff2(w3.x, hv.x, acc[3][j]);
                    acc[3][j] = ff2(w3.y, hv.y, acc[3][j]);
                }
            }

            if (kt < 7) {                  // commit prefetched tile
#pragma unroll
                for (int i = 0; i < 4; i++) {
                    const int g = tid + (i << 9); const int gb = g >> 5, gc = g & 31;
                    const int cs = gc ^ ((gb >> 2) & 7);
                    *(float4*)(snxt + gb * 128 + (cs << 2)) = pf[i];
                }
            }
        }

        // ---- fold pairs, cross-slice reduction (stride 17: conflict-free)
#pragma unroll
        for (int i = 0; i < 4; i++)
#pragma unroll
            for (int j = 0; j < 4; j++) {
                float lo, hi; upk2(acc[i][j], lo, hi);
                sred[ks * 2176 + pos * 17 + (i << 2) + j] = lo + hi;
            }
        __syncthreads();

        // ---- gate math + state update (1 cell/thread)
        // cell (gate q, unit jl, batch b): writer pos' has rb=jl, bb=b>>2,
        // slot q*4 + (b&3); pos' = ((b>>2)&7) | (jl<<3) | ((b>>5)<<6)
        {
            const int base = ((((b >> 2) & 7) | (jl << 3) | ((b >> 5) << 6))) * 17 + (b & 3);
            float gs[4];
#pragma unroll
            for (int q = 0; q < 4; q++) {
                const int idx = base + (q << 2);
                gs[q] = sred[idx] + sred[2176 + idx] + sred[4352 + idx] + sred[6528 + idx]
                        + xg[q] + bh[q];
            }
            const float ig = sigm(gs[0]), fg = sigm(gs[1]);
            const float gg = tanhf(gs[2]), og = sigm(gs[3]);
            creg = fg * creg + ig * gg;
            hlast = og * tanhf(creg);
            hwrite[b * NH + j0 + jl] = hlast;
        }

        grid_barrier();
    }

    // ---- outputs: [sig_out(64) | h(64x1024) | c(64x1024)]
    if (out_size >= 64 + NB * NH)
        out[64 + b * NH + j0 + jl] = hlast;
    if (out_size >= 64 + 2 * NB * NH)
        out[64 + NB * NH + b * NH + j0 + jl] = creg;
    if (cta == 0 && tid < 64 && out_size >= 64) {
        const float* hfin = g_hbuf[0];     // NS even -> final h in buffer 0
        float a = fc_b[0];
        for (int k = 0; k < NH; k += 4) {
            const float4 hv = __ldcg((const float4*)(hfin + tid * NH + k));
            const float4 wv = *(const float4*)(fc_w + k);
            a += hv.x * wv.x; a += hv.y * wv.y; a += hv.z * wv.z; a += hv.w * wv.w;
        }
        out[tid] = sigm(a);
    }
}

// =====================================================================
extern "C" void kernel_launch(void* const* d_in, const int* in_sizes, int n_in,
                              void* d_out, int out_size)
{
    const int*   x    = (const int*)d_in[0];
    const float* h0   = (const float*)d_in[1];
    const float* c0   = (const float*)d_in[2];
    const float* emb  = (const float*)d_in[3];
    const float* W_ih = (const float*)d_in[4];
    const float* W_hh = (const float*)d_in[5];
    const float* b_ih = (const float*)d_in[6];
    const float* b_hh = (const float*)d_in[7];
    const float* fc_w = (const float*)d_in[8];
    const float* fc_b = (const float*)d_in[9];
    float* out = (float*)d_out;

    const int lstm_smem = (32 * 1028 + 2 * 8192 + 4 * 2176) * (int)sizeof(float); // 231936 B
    cudaFuncSetAttribute(lstm_kernel, cudaFuncAttributeMaxDynamicSharedMemorySize, lstm_smem);

    dim3 grid_x(32, 256);                                 // N-tiles x M-tiles
    xproj_kernel<<<grid_x, 256>>>(x, emb, W_ih, b_ih);
    lstm_kernel<<<NCTA, 512, lstm_smem>>>(h0, c0, W_hh, b_hh, fc_w, fc_b, out, out_size);
}

// round 17
// speedup vs baseline: 1.3874x; 1.0708x over previous
#include <cuda_runtime.h>
#include <cstdint>
#include <cstddef>

#define NB    64      // batch
#define NS    512     // seq len
#define NE    512     // embed dim
#define NH    1024    // hidden
#define NG    4096    // 4*H
#define NCTA  128     // persistent CTAs (1 per SM)

typedef unsigned long long u64;

// ---------------- scratch (device globals: sanctioned, no allocation) ----------------
__device__ float g_xproj[(size_t)NS * NB * NG];   // 512 MB: [s][b][4H]
__device__ float g_hbuf[2][NB * NH];              // double-buffered h
__device__ u64 g_bar_ticket;                      // monotonic arrival tickets
__device__ u64 g_bar_gen;                         // monotonic release count

__device__ __forceinline__ float sigm(float v) { return 1.0f / (1.0f + __expf(-v)); }

// ---- packed fp32x2 helpers ----
__device__ __forceinline__ u64 pk2(float lo, float hi) {
    u64 r; asm("mov.b64 %0, {%1, %2};" : "=l"(r) : "f"(lo), "f"(hi)); return r;
}
__device__ __forceinline__ void upk2(u64 v, float& lo, float& hi) {
    asm("mov.b64 {%0, %1}, %2;" : "=f"(lo), "=f"(hi) : "l"(v));
}
__device__ __forceinline__ u64 ff2(u64 a, u64 b, u64 c) {   // a*b + c, both lanes
    u64 d; asm("fma.rn.f32x2 %0, %1, %2, %3;" : "=l"(d) : "l"(a), "l"(b), "l"(c)); return d;
}

// =====================================================================
// Kernel A: xproj — unchanged from R9/R12 (already ~1.0 RF-B/FMA).
// =====================================================================
#define AST 140

__global__ __launch_bounds__(256, 2)
void xproj_kernel(const int* __restrict__ x,
                  const float* __restrict__ emb,
                  const float* __restrict__ W_ih,
                  const float* __restrict__ b_ih)
{
    __shared__ __align__(16) float As[16 * AST];
    __shared__ __align__(16) float Bs[16 * AST];

    const int tid = threadIdx.x;
    const int nt = blockIdx.x;
    const int mt = blockIdx.y;
    const int m0 = mt * 128;
    const int n0 = nt * 128;

    const int lrow = tid >> 2;
    const int lch  = tid & 3;

    const int mA0 = m0 + lrow;
    const int mA1 = mA0 + 64;
    const int tok0 = x[(mA0 & 63) * NS + (mA0 >> 6)];
    const int tok1 = x[(mA1 & 63) * NS + (mA1 >> 6)];
    const float4* a0p = (const float4*)(emb + (size_t)tok0 * NE);
    const float4* a1p = (const float4*)(emb + (size_t)tok1 * NE);
    const float4* b0p = (const float4*)(W_ih + (size_t)(n0 + lrow) * NE);
    const float4* b1p = (const float4*)(W_ih + (size_t)(n0 + lrow + 64) * NE);

    const int tx = tid & 15;
    const int ty = tid >> 4;

    const int pm0 = lrow + ((lrow >> 5) << 2);
    const int pm1 = (lrow + 64) + (((lrow + 64) >> 5) << 2);
    const int pa  = ty * 8 + ((ty >> 2) << 2);
    const int pb  = tx * 8 + ((tx >> 2) << 2);

    u64 acc[8][4];
#pragma unroll
    for (int i = 0; i < 8; i++)
#pragma unroll
        for (int jp = 0; jp < 4; jp++) acc[i][jp] = 0ull;

    float4 av0 = a0p[lch], av1 = a1p[lch], bv0 = b0p[lch], bv1 = b1p[lch];

    for (int kt = 0; kt < 32; kt++) {
        const int kl = lch * 4;
        As[(kl + 0) * AST + pm0] = av0.x; As[(kl + 1) * AST + pm0] = av0.y;
        As[(kl + 2) * AST + pm0] = av0.z; As[(kl + 3) * AST + pm0] = av0.w;
        As[(kl + 0) * AST + pm1] = av1.x; As[(kl + 1) * AST + pm1] = av1.y;
        As[(kl + 2) * AST + pm1] = av1.z; As[(kl + 3) * AST + pm1] = av1.w;
        Bs[(kl + 0) * AST + pm0] = bv0.x; Bs[(kl + 1) * AST + pm0] = bv0.y;
        Bs[(kl + 2) * AST + pm0] = bv0.z; Bs[(kl + 3) * AST + pm0] = bv0.w;
        Bs[(kl + 0) * AST + pm1] = bv1.x; Bs[(kl + 1) * AST + pm1] = bv1.y;
        Bs[(kl + 2) * AST + pm1] = bv1.z; Bs[(kl + 3) * AST + pm1] = bv1.w;
        __syncthreads();

        if (kt < 31) {
            const int kc = (kt + 1) * 4 + lch;
            av0 = a0p[kc]; av1 = a1p[kc]; bv0 = b0p[kc]; bv1 = b1p[kc];
        }

#pragma unroll
        for (int k = 0; k < 16; k++) {
            const float4 aa0 = *(const float4*)&As[k * AST + pa];
            const float4 aa1 = *(const float4*)&As[k * AST + pa + 4];
            const ulonglong2 bq0 = *(const ulonglong2*)&Bs[k * AST + pb];
            const ulonglong2 bq1 = *(const ulonglong2*)&Bs[k * AST + pb + 4];
            const u64 b2[4] = {bq0.x, bq0.y, bq1.x, bq1.y};
            const float a[8] = {aa0.x, aa0.y, aa0.z, aa0.w, aa1.x, aa1.y, aa1.z, aa1.w};
#pragma unroll
            for (int i = 0; i < 8; i++) {
                const u64 ad = pk2(a[i], a[i]);
#pragma unroll
                for (int jp = 0; jp < 4; jp++)
                    acc[i][jp] = ff2(ad, b2[jp], acc[i][jp]);
            }
        }
        __syncthreads();
    }

    float bias[8];
#pragma unroll
    for (int j = 0; j < 8; j++) bias[j] = b_ih[n0 + tx * 8 + j];
#pragma unroll
    for (int i = 0; i < 8; i++) {
        float o[8];
#pragma unroll
        for (int jp = 0; jp < 4; jp++) upk2(acc[i][jp], o[2 * jp], o[2 * jp + 1]);
        const size_t base = (size_t)(m0 + ty * 8 + i) * NG + (n0 + tx * 8);
        float4 o0, o1;
        o0.x = o[0] + bias[0]; o0.y = o[1] + bias[1];
        o0.z = o[2] + bias[2]; o0.w = o[3] + bias[3];
        o1.x = o[4] + bias[4]; o1.y = o[5] + bias[5];
        o1.z = o[6] + bias[6]; o1.w = o[7] + bias[7];
        __stcs((float4*)&g_xproj[base], o0);
        __stcs((float4*)&g_xproj[base + 4], o1);
    }
}

// =====================================================================
// Replay-safe grid barrier (monotonic u64 ticket/gen, proven in R12).
// =====================================================================
__device__ __forceinline__ void grid_barrier()
{
    __syncthreads();
    if (threadIdx.x == 0) {
        __threadfence();
        const u64 t = atomicAdd(&g_bar_ticket, 1ull);
        const u64 inst = t / NCTA;
        if ((t % NCTA) == NCTA - 1) {
            atomicAdd(&g_bar_gen, 1ull);
        } else {
            while (*((volatile u64*)&g_bar_gen) <= inst) { }
        }
        __threadfence();
    }
    __syncthreads();
}

// =====================================================================
// Kernel B: persistent LSTM recurrence — row-pair FFMA2, 1.0 RF-B/FMA.
// 256 threads, 8 warps. W_hh slice stored K-MAJOR: swt[k][32 rows]
// (rows contiguous -> one LDS.128 = 2 row-pairs for fma.f32x2).
// Register tile per thread: 8 rows (4 pairs) x 8 batches, k-split 8
// (warp w handles chunks {w, w+8} of each 64-k tile).
// h tiles [64][64] double-buffered; chunk swizzle c' = kq ^ (b>>3):
// reader conflict-degree 1, writer degree 4 (= free at 4-wf RF floor).
// =====================================================================
__global__ __launch_bounds__(256, 1)
void lstm_kernel(const float* __restrict__ h0, const float* __restrict__ c0,
                 const float* __restrict__ W_hh, const float* __restrict__ b_hh,
                 const float* __restrict__ fc_w, const float* __restrict__ fc_b,
                 float* __restrict__ out, int out_size)
{
    extern __shared__ __align__(16) float smem[];
    float* swt  = smem;                 // [1024][32] k-major W slice (131072 B)
    float* shb  = smem + 32768;         // 2 x [64][64] h tiles        ( 32768 B)
    float* sred = shb + 8192;           // [256][66] partials          ( 67584 B)
                                        // total 231424 B <= 232448

    const int tid = threadIdx.x;
    const int cta = blockIdx.x;
    const int j0 = cta * 8;

    // ---- W_hh slice, transposed to k-major: swt[k*32 + r] = W_hh[grow(r)][k]
    // local row r = gate q*8 + unit u  ->  global row q*NH + j0 + u
    for (int idx = tid; idx < 8192; idx += 256) {
        const int r = idx >> 8;             // 0..31
        const int kc = idx & 255;           // float4 k-chunk
        const int grow = (r >> 3) * NH + j0 + (r & 7);
        const float4 v = *(const float4*)(W_hh + (size_t)grow * NH + kc * 4);
        swt[(kc * 4 + 0) * 32 + r] = v.x;
        swt[(kc * 4 + 1) * 32 + r] = v.y;
        swt[(kc * 4 + 2) * 32 + r] = v.z;
        swt[(kc * 4 + 3) * 32 + r] = v.w;
    }

    const int lane = tid & 31;
    const int warp = tid >> 5;              // k-slice 0..7
    const int rg   = lane >> 3;             // row group (8 rows)
    const int bg   = lane & 7;              // batch group (8 batches)

    // ---- state: 2 (batch, unit) cells per thread
    int   cb[2], cu[2];
    float creg[2], hlast[2], bh[2][4];
#pragma unroll
    for (int u2 = 0; u2 < 2; u2++) {
        const int cell = tid + (u2 << 8);   // 0..511
        cb[u2] = cell & 63;
        cu[u2] = cell >> 6;                 // 0..7
        creg[u2] = c0[cb[u2] * NH + j0 + cu[u2]];
        g_hbuf[0][cb[u2] * NH + j0 + cu[u2]] = h0[cb[u2] * NH + j0 + cu[u2]];
        hlast[u2] = 0.0f;
#pragma unroll
        for (int q = 0; q < 4; q++) bh[u2][q] = b_hh[q * NH + j0 + cu[u2]];
    }

    grid_barrier();                         // swt + h0 visible

    for (int s = 0; s < NS; s++) {
        const float* hread  = g_hbuf[s & 1];
        float*       hwrite = g_hbuf[(s + 1) & 1];

        // xproj gate inputs (latency hidden under GEMM)
        float xg[2][4];
#pragma unroll
        for (int u2 = 0; u2 < 2; u2++)
#pragma unroll
            for (int q = 0; q < 4; q++)
                xg[u2][q] = __ldcg(&g_xproj[((size_t)s * NB + cb[u2]) * NG + q * NH + j0 + cu[u2]]);

        u64 acc[4][8];                      // [row-pair][batch]
#pragma unroll
        for (int i = 0; i < 4; i++)
#pragma unroll
            for (int j = 0; j < 8; j++) acc[i][j] = 0ull;

        // prologue: tile 0 (1024 float4 / 256 thr = 4 each)
        float4 pf[4];
#pragma unroll
        for (int i = 0; i < 4; i++) {
            const int idx = tid + (i << 8); const int gb = idx >> 4, gc = idx & 15;
            pf[i] = __ldcg((const float4*)(hread + gb * NH + (gc << 2)));
        }
#pragma unroll
        for (int i = 0; i < 4; i++) {
            const int idx = tid + (i << 8); const int gb = idx >> 4, gc = idx & 15;
            *(float4*)(shb + (gb << 6) + ((gc ^ (gb >> 3)) << 2)) = pf[i];
        }

#pragma unroll 2
        for (int kt = 0; kt < 16; kt++) {
            __syncthreads();
            const float* scur = shb + ((kt & 1) << 12);
            float*       snxt = shb + (((kt + 1) & 1) << 12);

            if (kt < 15) {                  // prefetch next tile under compute
#pragma unroll
                for (int i = 0; i < 4; i++) {
                    const int idx = tid + (i << 8); const int gb = idx >> 4, gc = idx & 15;
                    pf[i] = __ldcg((const float4*)(hread + gb * NH + ((kt + 1) << 6) + (gc << 2)));
                }
            }

#pragma unroll
            for (int kqi = 0; kqi < 2; kqi++) {
                const int kq = warp + (kqi << 3);    // chunk 0..15 within tile
                // h operands: 8 batches x 4 k's (swizzled chunk)
                float4 hv[8];
#pragma unroll
                for (int j = 0; j < 8; j++)
                    hv[j] = *(const float4*)(scur + (((bg << 3) + j) << 6) + ((kq ^ bg) << 2));
#pragma unroll
                for (int kk = 0; kk < 4; kk++) {
                    const int krow = (kt << 6) + (kq << 2) + kk;
                    const ulonglong2 wa = *(const ulonglong2*)(swt + krow * 32 + (rg << 3));
                    const ulonglong2 wb = *(const ulonglong2*)(swt + krow * 32 + (rg << 3) + 4);
#pragma unroll
                    for (int j = 0; j < 8; j++) {
                        const float hs = (kk == 0) ? hv[j].x : (kk == 1) ? hv[j].y
                                       : (kk == 2) ? hv[j].z : hv[j].w;
                        const u64 hd = pk2(hs, hs);    // ALU mov, hidden under FMA
                        acc[0][j] = ff2(wa.x, hd, acc[0][j]);
                        acc[1][j] = ff2(wa.y, hd, acc[1][j]);
                        acc[2][j] = ff2(wb.x, hd, acc[2][j]);
                        acc[3][j] = ff2(wb.y, hd, acc[3][j]);
                    }
                }
            }

            if (kt < 15) {                  // commit prefetched tile
#pragma unroll
                for (int i = 0; i < 4; i++) {
                    const int idx = tid + (i << 8); const int gb = idx >> 4, gc = idx & 15;
                    *(float4*)(snxt + (gb << 6) + ((gc ^ (gb >> 3)) << 2)) = pf[i];
                }
            }
        }

        // ---- per-slice partials: writer-major, STS.64 of row-pairs
        // cell (row rg*8+2rp+p, batch bg*8+j) at sred[tid*66 + j*8 + rp*2 + p]
#pragma unroll
        for (int rp = 0; rp < 4; rp++)
#pragma unroll
            for (int j = 0; j < 8; j++)
                *(u64*)(sred + tid * 66 + (j << 3) + (rp << 1)) = acc[rp][j];
        __syncthreads();

        // ---- gate math + state update (2 cells/thread)
#pragma unroll
        for (int u2 = 0; u2 < 2; u2++) {
            const int b = cb[u2], u = cu[u2];
            const int co = ((b & 7) << 3) + (((u & 7) >> 1) << 1) + (u & 1);
            float gs[4];
#pragma unroll
            for (int q = 0; q < 4; q++) {
                const int wl = (q << 3) + (b >> 3);   // writer lane
                float a = xg[u2][q] + bh[u2][q];
#pragma unroll
                for (int w = 0; w < 8; w++)
                    a += sred[(w * 32 + wl) * 66 + co];
                gs[q] = a;
            }
            const float ig = sigm(gs[0]), fg = sigm(gs[1]);
            const float gg = tanhf(gs[2]), og = sigm(gs[3]);
            creg[u2] = fg * creg[u2] + ig * gg;
            hlast[u2] = og * tanhf(creg[u2]);
            hwrite[b * NH + j0 + u] = hlast[u2];
        }

        grid_barrier();
    }

    // ---- outputs: [sig_out(64) | h(64x1024) | c(64x1024)]
#pragma unroll
    for (int u2 = 0; u2 < 2; u2++) {
        if (out_size >= 64 + NB * NH)
            out[64 + cb[u2] * NH + j0 + cu[u2]] = hlast[u2];
        if (out_size >= 64 + 2 * NB * NH)
            out[64 + NB * NH + cb[u2] * NH + j0 + cu[u2]] = creg[u2];
    }
    if (cta == 0 && tid < 64 && out_size >= 64) {
        const float* hfin = g_hbuf[0];      // NS even -> final h in buffer 0
        float a = fc_b[0];
        for (int k = 0; k < NH; k += 4) {
            const float4 hv = __ldcg((const float4*)(hfin + tid * NH + k));
            const float4 wv = *(const float4*)(fc_w + k);
            a += hv.x * wv.x; a += hv.y * wv.y; a += hv.z * wv.z; a += hv.w * wv.w;
        }
        out[tid] = sigm(a);
    }
}

// =====================================================================
extern "C" void kernel_launch(void* const* d_in, const int* in_sizes, int n_in,
                              void* d_out, int out_size)
{
    const int*   x    = (const int*)d_in[0];
    const float* h0   = (const float*)d_in[1];
    const float* c0   = (const float*)d_in[2];
    const float* emb  = (const float*)d_in[3];
    const float* W_ih = (const float*)d_in[4];
    const float* W_hh = (const float*)d_in[5];
    const float* b_ih = (const float*)d_in[6];
    const float* b_hh = (const float*)d_in[7];
    const float* fc_w = (const float*)d_in[8];
    const float* fc_b = (const float*)d_in[9];
    float* out = (float*)d_out;

    const int lstm_smem = (32768 + 8192 + 256 * 66) * (int)sizeof(float); // 231424 B
    cudaFuncSetAttribute(lstm_kernel, cudaFuncAttributeMaxDynamicSharedMemorySize, lstm_smem);

    dim3 grid_x(32, 256);                                 // N-tiles x M-tiles
    xproj_kernel<<<grid_x, 256>>>(x, emb, W_ih, b_ih);
    lstm_kernel<<<NCTA, 256, lstm_smem>>>(h0, c0, W_hh, b_hh, fc_w, fc_b, out, out_size);
}